// round 15
// baseline (speedup 1.0000x reference)
#include <cuda_runtime.h>
#include <cstdint>

#define NLEV 5
#define NTOT 3800
#define CAND_MAX 6000
#define ECAP 4096
#define ANCH_PER_BLK 64
#define NELEM 4264000
#define KCLAMP 0xFFFFFFu

__constant__ int c_abcum[NLEV + 1] = {0, 625, 782, 822, 832, 835};
__constant__ int c_anch[NLEV]      = {40000, 10000, 2500, 640, 160};
__constant__ int c_ebase[NLEV + 1] = {0, 3200000, 4000000, 4200000, 4251200, 4264000};
__constant__ int c_k[NLEV]         = {1000, 1000, 1000, 640, 160};
__constant__ int c_obase[NLEV + 1] = {0, 1000, 2000, 3000, 3640, 3800};

struct Ptrs { const float* cls[NLEV]; const float* ctn[NLEV]; const float* box[NLEV]; };

__device__ unsigned int       g_bits[NELEM];   // 24-bit proxy keys (asc = worse)
__device__ unsigned int       g_histA[NLEV][4096];
__device__ unsigned int       g_histB[NLEV][4096];
__device__ unsigned int       g_thrA[NLEV];
__device__ unsigned int       g_cumA[NLEV];
__device__ unsigned int       g_thr24[NLEV];
__device__ unsigned int       g_candCount[NLEV];
__device__ unsigned int       g_cand[NLEV][CAND_MAX];
__device__ unsigned long long g_gkey[NTOT];
__device__ float              g_scoresv[NTOT];
__device__ unsigned char      g_validv[NTOT];
__device__ float4             g_boxesv[NTOT];
__device__ int                g_order[NTOT];
__device__ unsigned char      g_valid_o[NTOT];
__device__ float4             g_boxo[NTOT];
__device__ unsigned int       g_ecount;
__device__ unsigned long long g_edges[ECAP];

// Bit-exact replica of libdevice __nv_expf in-range path (exact scoring only).
__device__ __forceinline__ float nv_expf(float a) {
    float j = __fmaf_rn(1.442695f, a, 12582912.0f);
    j = __fsub_rn(j, 12582912.0f);
    float f = __fmaf_rn(j, -6.93145752e-1f, a);
    f = __fmaf_rn(j, -1.42860677e-6f, f);
    float r =            1.37805939e-3f;
    r = __fmaf_rn(r, f, 8.37312452e-3f);
    r = __fmaf_rn(r, f, 4.16695364e-2f);
    r = __fmaf_rn(r, f, 1.66664720e-1f);
    r = __fmaf_rn(r, f, 4.99999851e-1f);
    r = __fmaf_rn(r, f, 1.00000000e+0f);
    r = __fmaf_rn(r, f, 1.00000000e+0f);
    int i = (int)j;
    float s = __int_as_float((i << 23) + 0x3f800000);
    return __fmul_rn(r, s);
}
__device__ __forceinline__ float ref_sigmoid(float x) {
    return __fdiv_rn(1.0f, __fadd_rn(1.0f, nv_expf(-x)));
}
__device__ __forceinline__ float fast_exp(float a) {
    float y;
    asm("{ .reg .f32 t; mul.f32 t, %1, 0f3FB8AA3B; ex2.approx.f32 %0, t; }"
        : "=f"(y) : "f"(a));
    return y;
}
__device__ __forceinline__ float fast_log(float a) {
    float y;
    asm("{ .reg .f32 t; lg2.approx.f32 t, %1; mul.f32 %0, t, 0f3F317218; }"
        : "=f"(y) : "f"(a));
    return y;
}

// 24-bit key from proxy w = (1+e^-c)*rt; clamp w>=4 (provably outside top-k).
__device__ __forceinline__ unsigned keyof(float c, float rt, float T) {
    if (c <= T) return KCLAMP;
    float w = __fmul_rn(__fadd_rn(1.0f, fast_exp(-c)), rt);
    unsigned wb = __float_as_uint(w);
    return (wb >= 0x40800000u) ? KCLAMP : (wb - 0x3F800000u);
}

// Proxy scoring + stage-A histogram (spread over 4096 bins of w in [1,4)).
__global__ void k_score(Ptrs p) {
    int b = blockIdx.x;
    int l = NLEV - 1;
    while (b < c_abcum[l]) l--;
    int ab = (b - c_abcum[l]) * ANCH_PER_BLK;
    int nanch = min(ANCH_PER_BLK, c_anch[l] - ab);
    __shared__ unsigned sh[4096];
    __shared__ float srt[ANCH_PER_BLK], sT[ANCH_PER_BLK];
    for (int i = threadIdx.x; i < 4096; i += 256) sh[i] = 0;
    if (threadIdx.x < nanch) {
        float rt = __fadd_rn(1.0f, fast_exp(-p.ctn[l][ab + threadIdx.x]));
        srt[threadIdx.x] = rt;
        // c <= T  =>  (1+e^-c)*rt >= 4 guaranteed (0.002 pad over lg2 approx err)
        sT[threadIdx.x] = (rt >= 4.0f) ? 1e30f
                        : (-fast_log(__fdiv_rn(4.0f, rt) - 1.0f) - 0.002f);
    }
    __syncthreads();
    const float4* __restrict__ cls4 = (const float4*)p.cls[l] + ab * 20;
    uint4* __restrict__ bits4 = (uint4*)(g_bits + c_ebase[l]) + ab * 20;
    int qmax = nanch * 20;
    for (int q = threadIdx.x; q < qmax; q += 256) {
        float4 c = cls4[q];
        int a = q / 20;
        float rt = srt[a], T = sT[a];
        uint4 o;
        o.x = keyof(c.x, rt, T);
        o.y = keyof(c.y, rt, T);
        o.z = keyof(c.z, rt, T);
        o.w = keyof(c.w, rt, T);
        bits4[q] = o;
        if (o.x != KCLAMP) atomicAdd(&sh[o.x >> 12], 1u);
        if (o.y != KCLAMP) atomicAdd(&sh[o.y >> 12], 1u);
        if (o.z != KCLAMP) atomicAdd(&sh[o.z >> 12], 1u);
        if (o.w != KCLAMP) atomicAdd(&sh[o.w >> 12], 1u);
    }
    __syncthreads();
    for (int i = threadIdx.x; i < 4096; i += 256)
        if (sh[i]) atomicAdd(&g_histA[l][i], sh[i]);
}

// Ascending boundary-bin scan (smallest key = best score).
__global__ void k_scan(int phase) {
    __shared__ unsigned ss[256];
    int t = threadIdx.x;
    for (int l = 0; l < NLEV; l++) {
        const unsigned* h = phase ? g_histB[l] : g_histA[l];
        unsigned s = 0;
        #pragma unroll
        for (int q = 0; q < 16; q++) s += h[t * 16 + q];
        ss[t] = s;
        __syncthreads();
        if (t == 0) {
            unsigned need = phase ? ((unsigned)c_k[l] - g_cumA[l]) : (unsigned)c_k[l];
            unsigned cum = 0; int seg = 0;
            for (; seg < 255; seg++) { if (cum + ss[seg] >= need) break; cum += ss[seg]; }
            int bin = seg * 16 + 15;
            for (int bb = seg * 16; bb <= seg * 16 + 15; bb++) {
                unsigned cc = h[bb];
                if (cum + cc >= need) { bin = bb; break; }
                cum += cc;
            }
            if (!phase) { g_thrA[l] = (unsigned)bin; g_cumA[l] = cum; }
            else        g_thr24[l] = (g_thrA[l] << 12) | (unsigned)bin;
        }
        __syncthreads();
    }
}

__device__ __forceinline__ int level_of4(int gi) {
    int l = NLEV - 1;
    while (gi < c_ebase[l]) l--;
    return l;
}

// Refine boundary bin with the low 12 key bits.
__global__ void k_histB2() {
    const uint4* __restrict__ bits4 = (const uint4*)g_bits;
    for (int q = blockIdx.x * blockDim.x + threadIdx.x; q < NELEM / 4;
         q += gridDim.x * blockDim.x) {
        uint4 v = bits4[q];
        int l = level_of4(q * 4);
        unsigned thr = g_thrA[l];
        if ((v.x >> 12) == thr) atomicAdd(&g_histB[l][v.x & 0xFFFu], 1u);
        if ((v.y >> 12) == thr) atomicAdd(&g_histB[l][v.y & 0xFFFu], 1u);
        if ((v.z >> 12) == thr) atomicAdd(&g_histB[l][v.z & 0xFFFu], 1u);
        if ((v.w >> 12) == thr) atomicAdd(&g_histB[l][v.w & 0xFFFu], 1u);
    }
}

// Collect candidates: key <= thr24+64 (covers proxy error with 2.6x slack).
__global__ void k_collect2() {
    const uint4* __restrict__ bits4 = (const uint4*)g_bits;
    for (int q = blockIdx.x * blockDim.x + threadIdx.x; q < NELEM / 4;
         q += gridDim.x * blockDim.x) {
        uint4 v = bits4[q];
        int gi = q * 4;
        int l = level_of4(gi);
        unsigned thrC = g_thr24[l] + 64u;
        int i0 = gi - c_ebase[l];
        unsigned bb[4] = {v.x, v.y, v.z, v.w};
        #pragma unroll
        for (int c = 0; c < 4; c++) {
            if (bb[c] <= thrC) {
                unsigned pos = atomicAdd(&g_candCount[l], 1u);
                if (pos < CAND_MAX) g_cand[l][pos] = (unsigned)(i0 + c);
            }
        }
    }
}

// Exact-score candidates, rank exactly (score desc, idx asc), emit top-k.
__global__ void k_ranklevel(Ptrs p, float* out) {
    __shared__ unsigned long long s[CAND_MAX];
    int l = blockIdx.x, t = threadIdx.x;
    int cnt = (int)min(g_candCount[l], (unsigned)CAND_MAX);
    const float* __restrict__ cls = p.cls[l];
    const float* __restrict__ ctn = p.ctn[l];
    for (int i = t; i < cnt; i += 1024) {
        unsigned idx = g_cand[l][i];
        float sc = __fsqrt_rn(__fmul_rn(ref_sigmoid(cls[idx]),
                                        ref_sigmoid(ctn[idx / 80])));
        s[i] = ((unsigned long long)__float_as_uint(sc) << 32) | (unsigned)(~idx);
    }
    __syncthreads();
    int k = c_k[l];
    const float* __restrict__ box = p.box[l];
    for (int ci = t; ci < cnt; ci += 1024) {
        unsigned long long key = s[ci];
        int rank = 0;
        for (int j = 0; j < cnt; j++) rank += (s[j] > key);
        if (rank >= k) continue;
        unsigned bits = (unsigned)(key >> 32);
        unsigned idx  = ~(unsigned)(key & 0xFFFFFFFFu);
        float sc = __uint_as_float(bits);
        int label = idx % 80, anchor = idx / 80;
        bool valid = sc > 0.05f;
        float msc = valid ? sc : 0.0f;
        int g = c_obase[l] + rank;
        g_scoresv[g] = msc;
        g_validv[g]  = valid ? 1 : 0;
        g_gkey[g] = ((unsigned long long)__float_as_uint(msc) << 32) |
                    (unsigned)(~(unsigned)g);
        float4 b = *(const float4*)(box + (size_t)anchor * 4);
        float off = 2.0f * (float)label;
        g_boxesv[g] = make_float4(__fadd_rn(b.x, off), __fadd_rn(b.y, off),
                                  __fadd_rn(b.z, off), __fadd_rn(b.w, off));
        out[3800 + g] = (float)label;
        out[7600 + g * 4 + 0] = fminf(fmaxf(__fdiv_rn(b.x, 1600.0f), 0.0f), 1.0f);
        out[7600 + g * 4 + 1] = fminf(fmaxf(__fdiv_rn(b.y, 1600.0f), 0.0f), 1.0f);
        out[7600 + g * 4 + 2] = fminf(fmaxf(__fdiv_rn(b.z, 1600.0f), 0.0f), 1.0f);
        out[7600 + g * 4 + 3] = fminf(fmaxf(__fdiv_rn(b.w, 1600.0f), 0.0f), 1.0f);
    }
}

__device__ __forceinline__ int count_greater(const unsigned long long* a, int n,
                                             unsigned long long key) {
    int lo = 0, hi = n;
    while (lo < hi) {
        int mid = (lo + hi) >> 1;
        if (a[mid] > key) lo = mid + 1; else hi = mid;
    }
    return lo;
}

__global__ void k_rankall() {
    int g = blockIdx.x * blockDim.x + threadIdx.x;
    if (g >= NTOT) return;
    int l = NLEV - 1;
    while (g < c_obase[l]) l--;
    unsigned long long key = g_gkey[g];
    int grank = g - c_obase[l];
    #pragma unroll
    for (int l2 = 0; l2 < NLEV; l2++) {
        if (l2 == l) continue;
        grank += count_greater(g_gkey + c_obase[l2], c_k[l2], key);
    }
    g_order[grank] = g;
    g_valid_o[grank] = g_validv[g];
    g_boxo[grank] = g_boxesv[g];
}

// All-pairs IoU; divide only on actual intersection (same-label pairs only).
__global__ void k_mask() {
    int bx = blockIdx.x, by = blockIdx.y;
    if (bx < by) return;
    __shared__ float4 cb[64];
    __shared__ float ca[64];
    int t = threadIdx.x;
    int j0 = bx * 64 + t;
    if (j0 < NTOT) {
        float4 b = g_boxo[j0];
        cb[t] = b;
        ca[t] = __fmul_rn(fmaxf(__fsub_rn(b.z, b.x), 0.0f), fmaxf(__fsub_rn(b.w, b.y), 0.0f));
    } else { cb[t] = make_float4(-1e30f, -1e30f, -1e30f, -1e30f); ca[t] = 0.0f; }
    __syncthreads();
    int i = by * 64 + t;
    if (i >= NTOT) return;
    float4 r = g_boxo[i];
    float ra = __fmul_rn(fmaxf(__fsub_rn(r.z, r.x), 0.0f), fmaxf(__fsub_rn(r.w, r.y), 0.0f));
    #pragma unroll 4
    for (int c = 0; c < 64; c++) {
        int j = bx * 64 + c;
        if (j > i && j < NTOT) {
            float ix1 = fmaxf(r.x, cb[c].x), iy1 = fmaxf(r.y, cb[c].y);
            float ix2 = fminf(r.z, cb[c].z), iy2 = fminf(r.w, cb[c].w);
            float inter = __fmul_rn(fmaxf(__fsub_rn(ix2, ix1), 0.0f),
                                    fmaxf(__fsub_rn(iy2, iy1), 0.0f));
            if (inter > 0.0f) {
                float uni = __fsub_rn(__fadd_rn(ra, ca[c]), inter);
                float iou = __fdiv_rn(inter, fmaxf(uni, 1e-9f));
                if (iou > 0.6f) {
                    unsigned pos = atomicAdd(&g_ecount, 1u);
                    if (pos < ECAP)
                        g_edges[pos] = ((unsigned long long)(unsigned)i << 32) | (unsigned)j;
                }
            }
        }
    }
}

// Sort edges, greedy-walk, emit outputs; re-zero persistent state for replay.
__global__ void k_nms_final(float* out) {
    __shared__ unsigned long long se[ECAP];
    __shared__ unsigned long long sbm[64];
    int t = threadIdx.x;
    int E = (int)min(g_ecount, (unsigned)ECAP);
    for (int i = t; i < E; i += 1024) se[i] = g_edges[i];
    if (t < 64) sbm[t] = 0ull;
    __syncthreads();
    unsigned long long mykey[4]; int myrank[4]; int nk = 0;
    for (int i = t; i < E; i += 1024) {
        unsigned long long key = se[i];
        int rank = 0;
        for (int j = 0; j < E; j++) rank += (se[j] < key);
        mykey[nk] = key; myrank[nk] = rank; nk++;
    }
    for (int r = t; r < NTOT; r += 1024)
        if (g_valid_o[r]) atomicOr(&sbm[r >> 6], 1ull << (r & 63));
    __syncthreads();
    for (int q = 0; q < nk; q++) se[myrank[q]] = mykey[q];
    __syncthreads();
    if (t == 0) {
        for (int e = 0; e < E; e++) {
            unsigned long long k = se[e];
            int i = (int)(k >> 32), j = (int)(k & 0xFFFFFFFFu);
            if ((sbm[i >> 6] >> (i & 63)) & 1ull)
                sbm[j >> 6] &= ~(1ull << (j & 63));
        }
    }
    __syncthreads();
    for (int r = t; r < NTOT; r += 1024) {
        int g = g_order[r];
        bool k = (sbm[r >> 6] >> (r & 63)) & 1ull;
        out[g] = k ? g_scoresv[g] : 0.0f;
        out[22800 + g] = k ? 1.0f : 0.0f;
    }
    // re-zero persistent state so the next replay starts clean
    unsigned* ha = &g_histA[0][0];
    unsigned* hb = &g_histB[0][0];
    for (int i = t; i < NLEV * 4096; i += 1024) { ha[i] = 0; hb[i] = 0; }
    if (t < NLEV) g_candCount[t] = 0;
    if (t == 0) g_ecount = 0;
}

extern "C" void kernel_launch(void* const* d_in, const int* in_sizes, int n_in,
                              void* d_out, int out_size) {
    Ptrs p;
    if (in_sizes[0] == 3200000) {
        for (int l = 0; l < NLEV; l++) {
            p.cls[l] = (const float*)d_in[3 * l + 0];
            p.ctn[l] = (const float*)d_in[3 * l + 1];
            p.box[l] = (const float*)d_in[3 * l + 2];
        }
    } else {
        for (int l = 0; l < NLEV; l++) {
            p.box[l] = (const float*)d_in[l];
            p.cls[l] = (const float*)d_in[5 + l];
            p.ctn[l] = (const float*)d_in[10 + l];
        }
    }
    float* out = (float*)d_out;
    k_score<<<835, 256>>>(p);
    k_scan<<<1, 256>>>(0);
    k_histB2<<<2048, 256>>>();
    k_scan<<<1, 256>>>(1);
    k_collect2<<<2048, 256>>>();
    k_ranklevel<<<5, 1024>>>(p, out);
    k_rankall<<<4, 1024>>>();
    k_mask<<<dim3(60, 60), 64>>>();
    k_nms_final<<<1, 1024>>>(out);
}

// round 16
// speedup vs baseline: 1.3846x; 1.3846x over previous
#include <cuda_runtime.h>
#include <cstdint>

#define NLEV 5
#define NTOT 3800
#define CAND_MAX 6000
#define ECAP 4096
#define ANCH_PER_BLK 64
#define NELEM 4264000
#define NANCH 53300

__constant__ int c_abcum[NLEV + 1]    = {0, 625, 782, 822, 832, 835};
__constant__ int c_anch[NLEV]         = {40000, 10000, 2500, 640, 160};
__constant__ int c_anchbase[NLEV + 1] = {0, 40000, 50000, 52500, 53140, 53300};
__constant__ int c_ebase[NLEV + 1]    = {0, 3200000, 4000000, 4200000, 4251200, 4264000};
__constant__ int c_k[NLEV]            = {1000, 1000, 1000, 640, 160};
__constant__ int c_obase[NLEV + 1]    = {0, 1000, 2000, 3000, 3640, 3800};

struct Ptrs { const float* cls[NLEV]; const float* ctn[NLEV]; const float* box[NLEV]; };

__device__ unsigned int       g_bits[NELEM];
__device__ float              g_sctn[NANCH];
__device__ float              g_rctn[NANCH];
__device__ unsigned int       g_histA[NLEV][4096];
__device__ unsigned int       g_histB[NLEV][4096];
__device__ unsigned int       g_thrA[NLEV];
__device__ unsigned int       g_cumA[NLEV];
__device__ unsigned int       g_thr24[NLEV];
__device__ unsigned int       g_candCount[NLEV];
__device__ unsigned int       g_cand[NLEV][CAND_MAX];
__device__ unsigned long long g_gkey[NTOT];
__device__ float              g_scoresv[NTOT];
__device__ unsigned char      g_validv[NTOT];
__device__ float4             g_boxesv[NTOT];
__device__ int                g_order[NTOT];
__device__ unsigned char      g_valid_o[NTOT];
__device__ float4             g_boxo[NTOT];
__device__ unsigned int       g_ecount;
__device__ unsigned long long g_edges[ECAP];

// Bit-exact replica of libdevice __nv_expf in-range path.
__device__ __forceinline__ float nv_expf(float a) {
    float j = __fmaf_rn(1.442695f, a, 12582912.0f);
    j = __fsub_rn(j, 12582912.0f);
    float f = __fmaf_rn(j, -6.93145752e-1f, a);
    f = __fmaf_rn(j, -1.42860677e-6f, f);
    float r =            1.37805939e-3f;
    r = __fmaf_rn(r, f, 8.37312452e-3f);
    r = __fmaf_rn(r, f, 4.16695364e-2f);
    r = __fmaf_rn(r, f, 1.66664720e-1f);
    r = __fmaf_rn(r, f, 4.99999851e-1f);
    r = __fmaf_rn(r, f, 1.00000000e+0f);
    r = __fmaf_rn(r, f, 1.00000000e+0f);
    int i = (int)j;
    float s = __int_as_float((i << 23) + 0x3f800000);
    return __fmul_rn(r, s);
}
__device__ __forceinline__ float ref_sigmoid(float x) {
    return __fdiv_rn(1.0f, __fadd_rn(1.0f, nv_expf(-x)));
}
// Approx exp for the proxy pass only (MUFU.EX2; error covered by collect margin).
__device__ __forceinline__ float fast_exp(float a) {
    float y;
    asm("{ .reg .f32 t; mul.f32 t, %1, 0f3FB8AA3B; ex2.approx.f32 %0, t; }"
        : "=f"(y) : "f"(a));
    return y;
}

__global__ void k_init(Ptrs p) {
    int i = blockIdx.x * blockDim.x + threadIdx.x, st = gridDim.x * blockDim.x;
    unsigned* a = &g_histA[0][0]; unsigned* b = &g_histB[0][0];
    for (int t = i; t < NLEV * 4096; t += st) { a[t] = 0; b[t] = 0; }
    if (i == 0) g_ecount = 0;
    if (i < NLEV) g_candCount[i] = 0;
    for (int t = i; t < NANCH; t += st) {
        int l = NLEV - 1;
        while (t < c_anchbase[l]) l--;
        float tv = p.ctn[l][t - c_anchbase[l]];
        float e = nv_expf(-tv);
        g_sctn[t] = __fdiv_rn(1.0f, __fadd_rn(1.0f, e));
        g_rctn[t] = __fadd_rn(1.0f, fast_exp(-tv));
    }
}

// Proxy pass: w ~= (1+e^-c)*(1+e^-t). Cache bits + shared histA.
__global__ void k_score(Ptrs p) {
    int b = blockIdx.x;
    int l = NLEV - 1;
    while (b < c_abcum[l]) l--;
    int ab = (b - c_abcum[l]) * ANCH_PER_BLK;
    int nanch = min(ANCH_PER_BLK, c_anch[l] - ab);
    __shared__ unsigned sh[4096];
    for (int i = threadIdx.x; i < 4096; i += blockDim.x) sh[i] = 0;
    __syncthreads();
    const float4* __restrict__ cls4 = (const float4*)p.cls[l] + ab * 20;
    uint4* __restrict__ bits4 = (uint4*)(g_bits + c_ebase[l]) + ab * 20;
    const float* __restrict__ rctn = g_rctn + c_anchbase[l] + ab;
    int qmax = nanch * 20;
    for (int q = threadIdx.x; q < qmax; q += blockDim.x) {
        float4 c = cls4[q];
        float rt = rctn[q / 20];
        uint4 o;
        o.x = __float_as_uint(__fmul_rn(__fadd_rn(1.0f, fast_exp(-c.x)), rt));
        o.y = __float_as_uint(__fmul_rn(__fadd_rn(1.0f, fast_exp(-c.y)), rt));
        o.z = __float_as_uint(__fmul_rn(__fadd_rn(1.0f, fast_exp(-c.z)), rt));
        o.w = __float_as_uint(__fmul_rn(__fadd_rn(1.0f, fast_exp(-c.w)), rt));
        bits4[q] = o;
        atomicAdd(&sh[o.x >> 20], 1u);
        atomicAdd(&sh[o.y >> 20], 1u);
        atomicAdd(&sh[o.z >> 20], 1u);
        atomicAdd(&sh[o.w >> 20], 1u);
    }
    __syncthreads();
    for (int i = threadIdx.x; i < 4096; i += blockDim.x)
        if (sh[i]) atomicAdd(&g_histA[l][i], sh[i]);
}

// Parallel ascending boundary-bin scan: one block per level, 1024 threads,
// coalesced hist load + Hillis-Steele prefix over 1024 partials.
__global__ void k_scan(int phase) {
    int l = blockIdx.x;
    const unsigned* __restrict__ h = phase ? g_histB[l] : g_histA[l];
    __shared__ unsigned ssum[1024];
    __shared__ unsigned sbins[4096];
    int t = threadIdx.x;
    const uint4* h4 = (const uint4*)h;
    uint4 v = h4[t];
    sbins[t * 4 + 0] = v.x; sbins[t * 4 + 1] = v.y;
    sbins[t * 4 + 2] = v.z; sbins[t * 4 + 3] = v.w;
    unsigned s = v.x + v.y + v.z + v.w;
    ssum[t] = s;
    __syncthreads();
    for (int off = 1; off < 1024; off <<= 1) {
        unsigned add = (t >= off) ? ssum[t - off] : 0u;
        __syncthreads();
        ssum[t] += add;
        __syncthreads();
    }
    unsigned need = phase ? ((unsigned)c_k[l] - g_cumA[l]) : (unsigned)c_k[l];
    unsigned prev = (t == 0) ? 0u : ssum[t - 1];
    if (ssum[t] >= need && prev < need) {
        unsigned cum = prev;
        int bin = t * 4 + 3;
        #pragma unroll
        for (int q = 0; q < 4; q++) {
            unsigned cc = sbins[t * 4 + q];
            if (cum + cc >= need) { bin = t * 4 + q; break; }
            cum += cc;
        }
        if (!phase) { g_thrA[l] = (unsigned)bin; g_cumA[l] = cum; }
        else        g_thr24[l] = (g_thrA[l] << 12) | (unsigned)bin;
    }
}

__device__ __forceinline__ int level_of4(int gi) {
    int l = NLEV - 1;
    while (gi < c_ebase[l]) l--;
    return l;
}

__global__ void k_histB2() {
    const uint4* __restrict__ bits4 = (const uint4*)g_bits;
    for (int q = blockIdx.x * blockDim.x + threadIdx.x; q < NELEM / 4;
         q += gridDim.x * blockDim.x) {
        uint4 v = bits4[q];
        int l = level_of4(q * 4);
        unsigned thr = g_thrA[l];
        if ((v.x >> 20) == thr) atomicAdd(&g_histB[l][(v.x >> 8) & 0xFFFu], 1u);
        if ((v.y >> 20) == thr) atomicAdd(&g_histB[l][(v.y >> 8) & 0xFFFu], 1u);
        if ((v.z >> 20) == thr) atomicAdd(&g_histB[l][(v.z >> 8) & 0xFFFu], 1u);
        if ((v.w >> 20) == thr) atomicAdd(&g_histB[l][(v.w >> 8) & 0xFFFu], 1u);
    }
}

// Collect candidate indices: w-bits <= thr24+2 (proxy-error safety margin).
__global__ void k_collect2() {
    const uint4* __restrict__ bits4 = (const uint4*)g_bits;
    for (int q = blockIdx.x * blockDim.x + threadIdx.x; q < NELEM / 4;
         q += gridDim.x * blockDim.x) {
        uint4 v = bits4[q];
        int gi = q * 4;
        int l = level_of4(gi);
        unsigned thrC = g_thr24[l] + 2u;
        int i0 = gi - c_ebase[l];
        unsigned bb[4] = {v.x, v.y, v.z, v.w};
        #pragma unroll
        for (int c = 0; c < 4; c++) {
            if ((bb[c] >> 8) <= thrC) {
                unsigned pos = atomicAdd(&g_candCount[l], 1u);
                if (pos < CAND_MAX) g_cand[l][pos] = (unsigned)(i0 + c);
            }
        }
    }
}

// Exact-score the candidates, rank exactly (score desc, idx asc), emit top-k.
__global__ void k_ranklevel(Ptrs p, float* out) {
    __shared__ unsigned long long s[CAND_MAX];
    int l = blockIdx.x, t = threadIdx.x;
    int cnt = (int)min(g_candCount[l], (unsigned)CAND_MAX);
    const float* __restrict__ cls = p.cls[l];
    const float* __restrict__ sctn = g_sctn + c_anchbase[l];
    for (int i = t; i < cnt; i += 1024) {
        unsigned idx = g_cand[l][i];
        float sc = __fsqrt_rn(__fmul_rn(ref_sigmoid(cls[idx]), sctn[idx / 80]));
        s[i] = ((unsigned long long)__float_as_uint(sc) << 32) | (unsigned)(~idx);
    }
    __syncthreads();
    int k = c_k[l];
    const float* __restrict__ box = p.box[l];
    for (int ci = t; ci < cnt; ci += 1024) {
        unsigned long long key = s[ci];
        int rank = 0;
        for (int j = 0; j < cnt; j++) rank += (s[j] > key);
        if (rank >= k) continue;
        unsigned bits = (unsigned)(key >> 32);
        unsigned idx  = ~(unsigned)(key & 0xFFFFFFFFu);
        float sc = __uint_as_float(bits);
        int label = idx % 80, anchor = idx / 80;
        bool valid = sc > 0.05f;
        float msc = valid ? sc : 0.0f;
        int g = c_obase[l] + rank;
        g_scoresv[g] = msc;
        g_validv[g]  = valid ? 1 : 0;
        g_gkey[g] = ((unsigned long long)__float_as_uint(msc) << 32) |
                    (unsigned)(~(unsigned)g);
        float4 b = *(const float4*)(box + (size_t)anchor * 4);
        float off = 2.0f * (float)label;
        g_boxesv[g] = make_float4(__fadd_rn(b.x, off), __fadd_rn(b.y, off),
                                  __fadd_rn(b.z, off), __fadd_rn(b.w, off));
        out[3800 + g] = (float)label;
        out[7600 + g * 4 + 0] = fminf(fmaxf(__fdiv_rn(b.x, 1600.0f), 0.0f), 1.0f);
        out[7600 + g * 4 + 1] = fminf(fmaxf(__fdiv_rn(b.y, 1600.0f), 0.0f), 1.0f);
        out[7600 + g * 4 + 2] = fminf(fmaxf(__fdiv_rn(b.z, 1600.0f), 0.0f), 1.0f);
        out[7600 + g * 4 + 3] = fminf(fmaxf(__fdiv_rn(b.w, 1600.0f), 0.0f), 1.0f);
    }
}

__device__ __forceinline__ int count_greater(const unsigned long long* a, int n,
                                             unsigned long long key) {
    int lo = 0, hi = n;
    while (lo < hi) {
        int mid = (lo + hi) >> 1;
        if (a[mid] > key) lo = mid + 1; else hi = mid;
    }
    return lo;
}

__global__ void k_rankall() {
    int g = blockIdx.x * blockDim.x + threadIdx.x;
    if (g >= NTOT) return;
    int l = NLEV - 1;
    while (g < c_obase[l]) l--;
    unsigned long long key = g_gkey[g];
    int grank = g - c_obase[l];
    #pragma unroll
    for (int l2 = 0; l2 < NLEV; l2++) {
        if (l2 == l) continue;
        grank += count_greater(g_gkey + c_obase[l2], c_k[l2], key);
    }
    g_order[grank] = g;
    g_valid_o[grank] = g_validv[g];
    g_boxo[grank] = g_boxesv[g];
}

// All-pairs IoU; divide only when boxes actually intersect (same-label pairs).
__global__ void k_mask() {
    int bx = blockIdx.x, by = blockIdx.y;
    if (bx < by) return;
    __shared__ float4 cb[64];
    __shared__ float ca[64];
    int t = threadIdx.x;
    int j0 = bx * 64 + t;
    if (j0 < NTOT) {
        float4 b = g_boxo[j0];
        cb[t] = b;
        ca[t] = __fmul_rn(fmaxf(__fsub_rn(b.z, b.x), 0.0f), fmaxf(__fsub_rn(b.w, b.y), 0.0f));
    } else { cb[t] = make_float4(-1e30f, -1e30f, -1e30f, -1e30f); ca[t] = 0.0f; }
    __syncthreads();
    int i = by * 64 + t;
    if (i >= NTOT) return;
    float4 r = g_boxo[i];
    float ra = __fmul_rn(fmaxf(__fsub_rn(r.z, r.x), 0.0f), fmaxf(__fsub_rn(r.w, r.y), 0.0f));
    #pragma unroll 4
    for (int c = 0; c < 64; c++) {
        int j = bx * 64 + c;
        if (j > i && j < NTOT) {
            float ix1 = fmaxf(r.x, cb[c].x), iy1 = fmaxf(r.y, cb[c].y);
            float ix2 = fminf(r.z, cb[c].z), iy2 = fminf(r.w, cb[c].w);
            float inter = __fmul_rn(fmaxf(__fsub_rn(ix2, ix1), 0.0f),
                                    fmaxf(__fsub_rn(iy2, iy1), 0.0f));
            if (inter > 0.0f) {
                float uni = __fsub_rn(__fadd_rn(ra, ca[c]), inter);
                float iou = __fdiv_rn(inter, fmaxf(uni, 1e-9f));
                if (iou > 0.6f) {
                    unsigned pos = atomicAdd(&g_ecount, 1u);
                    if (pos < ECAP)
                        g_edges[pos] = ((unsigned long long)(unsigned)i << 32) | (unsigned)j;
                }
            }
        }
    }
}

// Single block: sort edges, greedy-walk them, emit keep + final outputs.
__global__ void k_nms_final(float* out) {
    __shared__ unsigned long long se[ECAP];
    __shared__ unsigned long long sbm[64];
    int t = threadIdx.x;
    int E = (int)min(g_ecount, (unsigned)ECAP);
    for (int i = t; i < E; i += 1024) se[i] = g_edges[i];
    if (t < 64) sbm[t] = 0ull;
    __syncthreads();
    unsigned long long mykey[4]; int myrank[4]; int nk = 0;
    for (int i = t; i < E; i += 1024) {
        unsigned long long key = se[i];
        int rank = 0;
        for (int j = 0; j < E; j++) rank += (se[j] < key);
        mykey[nk] = key; myrank[nk] = rank; nk++;
    }
    for (int r = t; r < NTOT; r += 1024)
        if (g_valid_o[r]) atomicOr(&sbm[r >> 6], 1ull << (r & 63));
    __syncthreads();
    for (int q = 0; q < nk; q++) se[myrank[q]] = mykey[q];
    __syncthreads();
    if (t == 0) {
        for (int e = 0; e < E; e++) {
            unsigned long long k = se[e];
            int i = (int)(k >> 32), j = (int)(k & 0xFFFFFFFFu);
            if ((sbm[i >> 6] >> (i & 63)) & 1ull)
                sbm[j >> 6] &= ~(1ull << (j & 63));
        }
    }
    __syncthreads();
    for (int r = t; r < NTOT; r += 1024) {
        int g = g_order[r];
        bool k = (sbm[r >> 6] >> (r & 63)) & 1ull;
        out[g] = k ? g_scoresv[g] : 0.0f;
        out[22800 + g] = k ? 1.0f : 0.0f;
    }
}

extern "C" void kernel_launch(void* const* d_in, const int* in_sizes, int n_in,
                              void* d_out, int out_size) {
    Ptrs p;
    if (in_sizes[0] == 3200000) {
        for (int l = 0; l < NLEV; l++) {
            p.cls[l] = (const float*)d_in[3 * l + 0];
            p.ctn[l] = (const float*)d_in[3 * l + 1];
            p.box[l] = (const float*)d_in[3 * l + 2];
        }
    } else {
        for (int l = 0; l < NLEV; l++) {
            p.box[l] = (const float*)d_in[l];
            p.cls[l] = (const float*)d_in[5 + l];
            p.ctn[l] = (const float*)d_in[10 + l];
        }
    }
    float* out = (float*)d_out;
    k_init<<<209, 256>>>(p);
    k_score<<<835, 256>>>(p);
    k_scan<<<5, 1024>>>(0);
    k_histB2<<<2048, 256>>>();
    k_scan<<<5, 1024>>>(1);
    k_collect2<<<2048, 256>>>();
    k_ranklevel<<<5, 1024>>>(p, out);
    k_rankall<<<4, 1024>>>();
    k_mask<<<dim3(60, 60), 64>>>();
    k_nms_final<<<1, 1024>>>(out);
}